// round 6
// baseline (speedup 1.0000x reference)
#include <cuda_runtime.h>
#include <math.h>
#include <stddef.h>

// ---------------- problem constants ----------------
#define Bdim 32
#define Tdim 12
#define Ndim 325
#define Ddim 128
#define Hdim 8
#define Fdim 512
#define BTN  124800          // B*T*N tokens
#define BNSEQ 10400          // B*N temporal sequences
#define BTSEQ 384            // B*T spatial sequences

// ---------------- scratch (no-alloc rule: __device__ globals) ----------------
static __device__ float g_qkv [(size_t)BTN * 384];   // 191.7 MB
static __device__ float g_attn[(size_t)BTN * 128];   //  63.9 MB
static __device__ float g_x1  [(size_t)BTN * 128];
static __device__ float g_x2  [(size_t)BTN * 128];
static __device__ float g_hbuf[(size_t)BTN * 512];   // 255.6 MB

__device__ __forceinline__ float gelu_tanh(float v) {
    // matches jax.nn.gelu(approximate=True)
    float c = 0.7978845608028654f * (v + 0.044715f * v * v * v);
    return 0.5f * v * (1.0f + tanhf(c));
}

// ---------------- register-tiled SGEMM: C[M,Nc] = A[M,KD] @ W[Nc,KD]^T + bias ----------------
// 128x128 block tile, 8x8 thread tile, 256 threads. M divisible by 128, Nc by 128, KD by 16.
#define GBM 128
#define GBN 128
#define GBK 16

template <int KD, bool DOGELU>
__global__ __launch_bounds__(256, 2) void gemm_bias_kernel(
    const float* __restrict__ A, const float* __restrict__ W,
    const float* __restrict__ bias, float* __restrict__ C, int Nc)
{
    __shared__ __align__(16) float As[GBK][GBM];
    __shared__ __align__(16) float Ws[GBK][GBN];
    const int mblk = blockIdx.y * GBM;
    const int nblk = blockIdx.x * GBN;
    const int tid  = threadIdx.x;
    const int tx   = tid & 15;      // n direction (16 threads * 8 cols)
    const int ty   = tid >> 4;      // m direction (16 threads * 8 rows)

    float acc[8][8];
#pragma unroll
    for (int i = 0; i < 8; i++)
#pragma unroll
        for (int j = 0; j < 8; j++) acc[i][j] = 0.0f;

    for (int k0 = 0; k0 < KD; k0 += GBK) {
#pragma unroll
        for (int l = 0; l < 2; l++) {
            int f  = tid + l * 256;         // 0..511
            int r  = f >> 2;                // row within tile (0..127)
            int kq = (f & 3) << 2;          // k quad (0,4,8,12)
            float4 va = *(const float4*)(A + (size_t)(mblk + r) * KD + k0 + kq);
            As[kq + 0][r] = va.x; As[kq + 1][r] = va.y;
            As[kq + 2][r] = va.z; As[kq + 3][r] = va.w;
            float4 vw = *(const float4*)(W + (size_t)(nblk + r) * KD + k0 + kq);
            Ws[kq + 0][r] = vw.x; Ws[kq + 1][r] = vw.y;
            Ws[kq + 2][r] = vw.z; Ws[kq + 3][r] = vw.w;
        }
        __syncthreads();
#pragma unroll
        for (int kk = 0; kk < GBK; kk++) {
            float a[8], w[8];
            *(float4*)&a[0] = *(const float4*)&As[kk][ty * 8];
            *(float4*)&a[4] = *(const float4*)&As[kk][ty * 8 + 4];
            *(float4*)&w[0] = *(const float4*)&Ws[kk][tx * 8];
            *(float4*)&w[4] = *(const float4*)&Ws[kk][tx * 8 + 4];
#pragma unroll
            for (int i = 0; i < 8; i++)
#pragma unroll
                for (int j = 0; j < 8; j++)
                    acc[i][j] = fmaf(a[i], w[j], acc[i][j]);
        }
        __syncthreads();
    }

#pragma unroll
    for (int i = 0; i < 8; i++) {
        size_t row = (size_t)(mblk + ty * 8 + i) * Nc;
#pragma unroll
        for (int j4 = 0; j4 < 8; j4 += 4) {
            int n = nblk + tx * 8 + j4;
            float4 bb = *(const float4*)(bias + n);
            float4 o;
            o.x = acc[i][j4 + 0] + bb.x;
            o.y = acc[i][j4 + 1] + bb.y;
            o.z = acc[i][j4 + 2] + bb.z;
            o.w = acc[i][j4 + 3] + bb.w;
            if (DOGELU) {
                o.x = gelu_tanh(o.x); o.y = gelu_tanh(o.y);
                o.z = gelu_tanh(o.z); o.w = gelu_tanh(o.w);
            }
            *(float4*)(C + row + n) = o;
        }
    }
}

// ---------------- SGEMM + bias + residual + LayerNorm, Nc = 128 fixed ----------------
// out = LN(res + A @ W^T + bias; gamma, beta). One block owns 128 complete rows.
template <int KD>
__global__ __launch_bounds__(256, 2) void gemm_res_ln_kernel(
    const float* __restrict__ A, const float* __restrict__ W,
    const float* __restrict__ bias, const float* __restrict__ res,
    const float* __restrict__ gam, const float* __restrict__ bet,
    float* __restrict__ C)
{
    __shared__ __align__(16) float As[GBK][GBM];
    __shared__ __align__(16) float Ws[GBK][128];
    __shared__ float redS[GBM][17];
    __shared__ float redQ[GBM][17];
    __shared__ float sMean[GBM];
    __shared__ float sRstd[GBM];

    const int mblk = blockIdx.x * GBM;
    const int tid  = threadIdx.x;
    const int tx   = tid & 15;
    const int ty   = tid >> 4;

    float acc[8][8];
#pragma unroll
    for (int i = 0; i < 8; i++)
#pragma unroll
        for (int j = 0; j < 8; j++) acc[i][j] = 0.0f;

    for (int k0 = 0; k0 < KD; k0 += GBK) {
#pragma unroll
        for (int l = 0; l < 2; l++) {
            int f  = tid + l * 256;
            int r  = f >> 2;
            int kq = (f & 3) << 2;
            float4 va = *(const float4*)(A + (size_t)(mblk + r) * KD + k0 + kq);
            As[kq + 0][r] = va.x; As[kq + 1][r] = va.y;
            As[kq + 2][r] = va.z; As[kq + 3][r] = va.w;
            float4 vw = *(const float4*)(W + (size_t)r * KD + k0 + kq);
            Ws[kq + 0][r] = vw.x; Ws[kq + 1][r] = vw.y;
            Ws[kq + 2][r] = vw.z; Ws[kq + 3][r] = vw.w;
        }
        __syncthreads();
#pragma unroll
        for (int kk = 0; kk < GBK; kk++) {
            float a[8], w[8];
            *(float4*)&a[0] = *(const float4*)&As[kk][ty * 8];
            *(float4*)&a[4] = *(const float4*)&As[kk][ty * 8 + 4];
            *(float4*)&w[0] = *(const float4*)&Ws[kk][tx * 8];
            *(float4*)&w[4] = *(const float4*)&Ws[kk][tx * 8 + 4];
#pragma unroll
            for (int i = 0; i < 8; i++)
#pragma unroll
                for (int j = 0; j < 8; j++)
                    acc[i][j] = fmaf(a[i], w[j], acc[i][j]);
        }
        __syncthreads();
    }

    // add bias + residual, accumulate row partial sums / sumsq
#pragma unroll
    for (int i = 0; i < 8; i++) {
        int lr = ty * 8 + i;
        int m  = mblk + lr;
        const float* rrow = res + (size_t)m * 128 + tx * 8;
        float4 r0 = *(const float4*)(rrow);
        float4 r1 = *(const float4*)(rrow + 4);
        float4 b0 = *(const float4*)(bias + tx * 8);
        float4 b1 = *(const float4*)(bias + tx * 8 + 4);
        acc[i][0] += b0.x + r0.x; acc[i][1] += b0.y + r0.y;
        acc[i][2] += b0.z + r0.z; acc[i][3] += b0.w + r0.w;
        acc[i][4] += b1.x + r1.x; acc[i][5] += b1.y + r1.y;
        acc[i][6] += b1.z + r1.z; acc[i][7] += b1.w + r1.w;
        float s = 0.0f, qq = 0.0f;
#pragma unroll
        for (int j = 0; j < 8; j++) { s += acc[i][j]; qq = fmaf(acc[i][j], acc[i][j], qq); }
        redS[lr][tx] = s;
        redQ[lr][tx] = qq;
    }
    __syncthreads();
    if (tid < 128) {
        float s = 0.0f, qq = 0.0f;
#pragma unroll
        for (int c = 0; c < 16; c++) { s += redS[tid][c]; qq += redQ[tid][c]; }
        float mean = s * (1.0f / 128.0f);
        float var  = qq * (1.0f / 128.0f) - mean * mean;
        sMean[tid] = mean;
        sRstd[tid] = rsqrtf(var + 1e-5f);
    }
    __syncthreads();
#pragma unroll
    for (int i = 0; i < 8; i++) {
        int lr = ty * 8 + i;
        float mean = sMean[lr], rstd = sRstd[lr];
        size_t row = (size_t)(mblk + lr) * 128;
#pragma unroll
        for (int j4 = 0; j4 < 8; j4 += 4) {
            int n = tx * 8 + j4;
            float4 g4 = *(const float4*)(gam + n);
            float4 b4 = *(const float4*)(bet + n);
            float4 o;
            o.x = (acc[i][j4 + 0] - mean) * rstd * g4.x + b4.x;
            o.y = (acc[i][j4 + 1] - mean) * rstd * g4.y + b4.y;
            o.z = (acc[i][j4 + 2] - mean) * rstd * g4.z + b4.z;
            o.w = (acc[i][j4 + 3] - mean) * rstd * g4.w + b4.w;
            *(float4*)(C + row + n) = o;
        }
    }
}

// ---------------- temporal attention: one block per (b, n) sequence, T=12 ----------------
__global__ __launch_bounds__(128) void temporal_attn_kernel(
    const float* __restrict__ qkv, float* __restrict__ attn)
{
    __shared__ __align__(16) float sq[Tdim][388];   // 12 x 384 (+4 pad)
    const int bn  = blockIdx.x;
    const int b   = bn / Ndim;
    const int n   = bn % Ndim;
    const int tid = threadIdx.x;

    for (int idx = tid; idx < Tdim * 96; idx += 128) {
        int t = idx / 96;
        int c = (idx % 96) * 4;
        size_t r = ((size_t)(b * Tdim + t) * Ndim + n) * 384;
        *(float4*)&sq[t][c] = *(const float4*)(qkv + r + c);
    }
    __syncthreads();

    if (tid < Hdim * Tdim) {
        const int h   = tid / Tdim;
        const int q   = tid % Tdim;
        const int off = h * 16;
        float qd[16];
#pragma unroll
        for (int d = 0; d < 16; d++) qd[d] = sq[q][off + d];

        float e[Tdim];
        float Z = 0.0f;
#pragma unroll
        for (int s = 0; s < Tdim; s++) {
            float sc = 0.0f;
#pragma unroll
            for (int d = 0; d < 16; d++) sc = fmaf(qd[d], sq[s][128 + off + d], sc);
            e[s] = __expf(sc * 0.25f);   // scores bounded; no max-sub needed
            Z += e[s];
        }
        float inv = 1.0f / Z;
        float o[16];
#pragma unroll
        for (int d = 0; d < 16; d++) {
            float a = 0.0f;
#pragma unroll
            for (int s = 0; s < Tdim; s++) a = fmaf(e[s], sq[s][256 + off + d], a);
            o[d] = a * inv;
        }
        size_t ro = ((size_t)(b * Tdim + q) * Ndim + n) * 128 + off;
#pragma unroll
        for (int c = 0; c < 16; c += 4) {
            float4 v; v.x = o[c]; v.y = o[c + 1]; v.z = o[c + 2]; v.w = o[c + 3];
            *(float4*)(attn + ro + c) = v;
        }
    }
}

// ---------------- spatial attention: one block per (bt, head), one lane per query ----------------
// K/V head slice in smem (no padding: compute reads are warp-broadcast -> conflict-free).
__global__ __launch_bounds__(352) void spatial_attn_kernel(
    const float* __restrict__ qkv, const float* __restrict__ gbias,
    float* __restrict__ attn)
{
    __shared__ __align__(16) float Ks[Ndim][16];
    __shared__ __align__(16) float Vs[Ndim][16];
    const int h   = blockIdx.x;
    const int bt  = blockIdx.y;
    const int tid = threadIdx.x;
    const size_t base = (size_t)bt * Ndim * 384;
    const int off = h * 16;

    for (int idx = tid; idx < Ndim * 4; idx += 352) {
        int j = idx >> 2;
        int c = (idx & 3) << 2;
        const float* p = qkv + base + (size_t)j * 384 + 128 + off + c;
        *(float4*)&Ks[j][c] = *(const float4*)p;          // K
        *(float4*)&Vs[j][c] = *(const float4*)(p + 128);  // V
    }
    __syncthreads();

    const int  q     = tid;
    const bool valid = (q < Ndim);
    const int  qc    = valid ? q : 0;

    float qr[16];
    const float* qp = qkv + base + (size_t)qc * 384 + off;
#pragma unroll
    for (int c = 0; c < 16; c += 4) {
        float4 v = *(const float4*)(qp + c);
        qr[c] = v.x; qr[c + 1] = v.y; qr[c + 2] = v.z; qr[c + 3] = v.w;
    }
    const float* brow = gbias + (size_t)qc * Ndim;

    float Z = 0.0f;
    float acc[16];
#pragma unroll
    for (int d = 0; d < 16; d++) acc[d] = 0.0f;

    for (int j = 0; j < Ndim; j++) {
        const float4* kr = (const float4*)Ks[j];
        float s = 0.0f;
#pragma unroll
        for (int c = 0; c < 4; c++) {
            float4 kk = kr[c];
            s = fmaf(qr[c * 4 + 0], kk.x, s);
            s = fmaf(qr[c * 4 + 1], kk.y, s);
            s = fmaf(qr[c * 4 + 2], kk.z, s);
            s = fmaf(qr[c * 4 + 3], kk.w, s);
        }
        float e = __expf(fmaf(s, 0.25f, __ldg(brow + j)));  // bounded scores
        Z += e;
        const float4* vr = (const float4*)Vs[j];
#pragma unroll
        for (int c = 0; c < 4; c++) {
            float4 vv = vr[c];
            acc[c * 4 + 0] = fmaf(e, vv.x, acc[c * 4 + 0]);
            acc[c * 4 + 1] = fmaf(e, vv.y, acc[c * 4 + 1]);
            acc[c * 4 + 2] = fmaf(e, vv.z, acc[c * 4 + 2]);
            acc[c * 4 + 3] = fmaf(e, vv.w, acc[c * 4 + 3]);
        }
    }

    if (valid) {
        float inv = 1.0f / Z;
        float* op = attn + ((size_t)bt * Ndim + q) * 128 + off;
#pragma unroll
        for (int c = 0; c < 16; c += 4) {
            float4 o;
            o.x = acc[c + 0] * inv; o.y = acc[c + 1] * inv;
            o.z = acc[c + 2] * inv; o.w = acc[c + 3] * inv;
            *(float4*)(op + c) = o;
        }
    }
}

// ---------------- launch ----------------
extern "C" void kernel_launch(void* const* d_in, const int* in_sizes, int n_in,
                              void* d_out, int out_size)
{
    const float* x       = (const float*)d_in[0];
    const float* t_w_in  = (const float*)d_in[1];
    const float* t_b_in  = (const float*)d_in[2];
    const float* t_w_out = (const float*)d_in[3];
    const float* t_b_out = (const float*)d_in[4];
    const float* s_w_in  = (const float*)d_in[5];
    const float* s_b_in  = (const float*)d_in[6];
    const float* s_w_out = (const float*)d_in[7];
    const float* s_b_out = (const float*)d_in[8];
    const float* gbias   = (const float*)d_in[9];
    const float* ntg     = (const float*)d_in[10];
    const float* ntb     = (const float*)d_in[11];
    const float* nsg     = (const float*)d_in[12];
    const float* nsb     = (const float*)d_in[13];
    const float* ffw1    = (const float*)d_in[14];
    const float* ffb1    = (const float*)d_in[15];
    const float* ffw2    = (const float*)d_in[16];
    const float* ffb2    = (const float*)d_in[17];
    const float* nfg     = (const float*)d_in[18];
    const float* nfb     = (const float*)d_in[19];
    float* out = (float*)d_out;

    float *qkv, *attn, *x1, *x2, *hbuf;
    cudaGetSymbolAddress((void**)&qkv,  g_qkv);
    cudaGetSymbolAddress((void**)&attn, g_attn);
    cudaGetSymbolAddress((void**)&x1,   g_x1);
    cudaGetSymbolAddress((void**)&x2,   g_x2);
    cudaGetSymbolAddress((void**)&hbuf, g_hbuf);

    const int MT = BTN / GBM;   // 975 (exact)

    // 1) temporal QKV
    gemm_bias_kernel<128, false><<<dim3(3, MT), 256>>>(x, t_w_in, t_b_in, qkv, 384);
    // 2) temporal attention
    temporal_attn_kernel<<<BNSEQ, 128>>>(qkv, attn);
    // 3) temporal out-proj + residual + LN -> x1
    gemm_res_ln_kernel<128><<<MT, 256>>>(attn, t_w_out, t_b_out, x, ntg, ntb, x1);
    // 4) spatial QKV
    gemm_bias_kernel<128, false><<<dim3(3, MT), 256>>>(x1, s_w_in, s_b_in, qkv, 384);
    // 5) spatial attention with graph bias
    spatial_attn_kernel<<<dim3(Hdim, BTSEQ), 352>>>(qkv, gbias, attn);
    // 6) spatial out-proj + residual + LN -> x2
    gemm_res_ln_kernel<128><<<MT, 256>>>(attn, s_w_out, s_b_out, x1, nsg, nsb, x2);
    // 7) FFN up + GELU
    gemm_bias_kernel<128, true><<<dim3(4, MT), 256>>>(x2, ffw1, ffb1, hbuf, 512);
    // 8) FFN down + residual + LN -> final output
    gemm_res_ln_kernel<512><<<MT, 256>>>(hbuf, ffw2, ffb2, x2, nfg, nfb, out);
}